// round 17
// baseline (speedup 1.0000x reference)
#include <cuda_runtime.h>
#include <cuda_fp16.h>
#include <math.h>
#include <stdint.h>

#define HH 1024
#define WW 1024
#define NHH 63
#define NP 3969
#define W1F 1017
#define W2F 1013
#define H1SZ (W1F * W1F)
#define H2SZ (W2F * W2F)

typedef unsigned long long ull;

// -------- global intermediates --------
__device__ uint32_t g_H1[(size_t)12 * H1SZ];     // fp16 channel-pair planes
__device__ uint32_t g_H2[(size_t)30 * H2SZ];
__device__ float    g_h3[(size_t)NP * 15000];    // deconv2 out, channel-paired float2
__device__ float    g_p[(size_t)NP * 1024];
__device__ uint2    g_Bc[40 * 8 * 32];           // conv2 B frags (fp16)
__device__ uint2    g_Bd2[100 * 3 * 32];         // deconv2 B frags (fp16, padded k, interleaved)

__device__ __forceinline__ float elu1(float v) { return v > 0.f ? v : expm1f(v); }
__device__ __forceinline__ uint32_t hpack(float a, float b) {
    return (uint32_t)__half_as_ushort(__float2half(a)) |
           ((uint32_t)__half_as_ushort(__float2half(b)) << 16);
}
__device__ __forceinline__ void fma2(ull &d, ull a, ull b) {
    asm("fma.rn.f32x2 %0, %1, %2, %0;" : "+l"(d) : "l"(a), "l"(b));
}
__device__ __forceinline__ float lo_f(ull u) { return __uint_as_float((unsigned)u); }
__device__ __forceinline__ float hi_f(ull u) { return __uint_as_float((unsigned)(u >> 32)); }

__device__ __forceinline__ void mma_f16(float d[4], const uint32_t a[4],
                                        uint32_t b0, uint32_t b1) {
    asm("mma.sync.aligned.m16n8k16.row.col.f32.f16.f16.f32 "
        "{%0,%1,%2,%3}, {%4,%5,%6,%7}, {%8,%9}, {%0,%1,%2,%3};"
        : "+f"(d[0]), "+f"(d[1]), "+f"(d[2]), "+f"(d[3])
        : "r"(a[0]), "r"(a[1]), "r"(a[2]), "r"(a[3]), "r"(b0), "r"(b1));
}

// deconv2 cluster channel map: position p (0..15) -> channel within 64-ch tap block
__host__ __device__ __forceinline__ int d2_ch(int c, int p) {
    int pl = (p < 8) ? (p & ~1) : (((p - 8) & ~1) + 1);
    return c * 16 + pl * 2 + (p & 1);
}

// ---------------- K0: pack B frag tables ----------------
__global__ void pack_kernel(const float* __restrict__ w2, const float* __restrict__ wd2) {
    int j = blockIdx.x * blockDim.x + threadIdx.x;
    if (j < 10240) {
        // conv2: idx=(kcl*8+nt)*32+lane; k = tap*24+ci, K=600 pad 640
        int lane = j & 31, nt = (j >> 5) & 7, kcl = j >> 8;
        int gid = lane >> 2, tig = lane & 3;
        int n = nt * 8 + gid;
        uint32_t fr[2];
#pragma unroll
        for (int s = 0; s < 2; s++) {
            int k = kcl * 16 + 2 * tig + s * 8;
            float v0 = 0.f, v1 = 0.f;
            if (n < 60 && k < 600) {
                int tap = k / 24, ci = k % 24;
                v0 = w2[n * 600 + ci * 25 + tap];
                v1 = w2[n * 600 + (ci + 1) * 25 + tap];
            }
            fr[s] = hpack(v0, v1);
        }
        g_Bc[j] = make_uint2(fr[0], fr[1]);
    } else if (j < 10240 + 9600) {
        // deconv2: idx=(kcl*3+nt)*32+lane; kcl = tap*4 + c; interleaved channel map
        int i = j - 10240;
        int lane = i & 31, nt = (i >> 5) % 3, kcl = i / 96;
        int gid = lane >> 2, tig = lane & 3;
        int r = nt * 8 + gid;            // < 24
        int tap = kcl >> 2, c = kcl & 3;
        uint32_t fr[2];
#pragma unroll
        for (int s = 0; s < 2; s++) {
            int p0 = 2 * tig + 8 * s;
            int ch0 = d2_ch(c, p0), ch1 = d2_ch(c, p0 + 1);
            float v0 = (ch0 < 60) ? wd2[ch0 * 600 + r * 25 + (24 - tap)] : 0.f;
            float v1 = (ch1 < 60) ? wd2[ch1 * 600 + r * 25 + (24 - tap)] : 0.f;
            fr[s] = hpack(v0, v1);
        }
        g_Bd2[i] = make_uint2(fr[0], fr[1]);
    }
}

// ---------------- K1: conv1 full-image (FFMA2) -> fp16 pair planes ----------------
__global__ void __launch_bounds__(256)
conv1_full_kernel(const float* __restrict__ x1, const float* __restrict__ x2,
                  const float* __restrict__ w, const float* __restrict__ b,
                  uint32_t* __restrict__ H1) {
    __shared__ float2 sImg[23 * 72];
    __shared__ float2 sW2[24 * 64];
    __shared__ float sB[24];
    const int gy0 = blockIdx.y * 16, gx0 = blockIdx.x * 64;
    const int tid = threadIdx.x;
    for (int i = tid; i < 23 * 72; i += 256) {
        int r = i / 72, c = i % 72;
        int gy = gy0 + r, gx = gx0 + c;
        float2 v = make_float2(0.f, 0.f);
        if (c < 71 && gy < 1024 && gx < 1024) {
            int g = gy * 1024 + gx;
            v = make_float2(x1[g], x2[g]);
        }
        sImg[i] = v;
    }
    for (int i = tid; i < 1536; i += 256) {
        int c = i >> 6, rem = i & 63;
        sW2[i] = make_float2(w[c * 128 + rem], w[c * 128 + 64 + rem]);
    }
    if (tid < 24) sB[tid] = b[tid];
    __syncthreads();
    const ull* sP = reinterpret_cast<const ull*>(sImg);
    const ull* sW = reinterpret_cast<const ull*>(sW2);
    const int y = tid >> 4, x0 = (tid & 15) * 4;
    const int gy = gy0 + y;
    for (int c0 = 0; c0 < 24; c0 += 4) {
        ull acc[4][4];
#pragma unroll
        for (int cc = 0; cc < 4; cc++)
#pragma unroll
            for (int j = 0; j < 4; j++) acc[cc][j] = 0ull;
#pragma unroll
        for (int ky = 0; ky < 8; ky++) {
            ull reg[11];
            const ull* row = sP + (y + ky) * 72 + x0;
#pragma unroll
            for (int i = 0; i < 11; i++) reg[i] = row[i];
#pragma unroll
            for (int cc = 0; cc < 4; cc++) {
                const ull* wr = sW + (c0 + cc) * 64 + ky * 8;
#pragma unroll
                for (int kx = 0; kx < 8; kx++) {
                    ull wv = wr[kx];
#pragma unroll
                    for (int j = 0; j < 4; j++) fma2(acc[cc][j], reg[j + kx], wv);
                }
            }
        }
        if (gy < W1F) {
#pragma unroll
            for (int pp = 0; pp < 2; pp++) {
                int cp = (c0 >> 1) + pp;
                float b0 = sB[c0 + 2 * pp], b1 = sB[c0 + 2 * pp + 1];
#pragma unroll
                for (int j = 0; j < 4; j++) {
                    int gx = gx0 + x0 + j;
                    if (gx < W1F) {
                        float v0 = elu1(lo_f(acc[2 * pp][j]) + hi_f(acc[2 * pp][j]) + b0);
                        float v1 = elu1(lo_f(acc[2 * pp + 1][j]) + hi_f(acc[2 * pp + 1][j]) + b1);
                        H1[(size_t)cp * H1SZ + gy * W1F + gx] = hpack(v0, v1);
                    }
                }
            }
        }
    }
}

// ---------------- K2: conv2 full-image GEMM (fp16 1-term) -> H2 ----------------
#define C2_PS 9768
#define C2_SMEM (C2_PS * 4 + 320 * 4)
__global__ void __launch_bounds__(256, 2)
conv2_full_kernel(const uint32_t* __restrict__ H1, const float* __restrict__ bias,
                  uint32_t* __restrict__ H2) {
    extern __shared__ uint32_t s32[];
    uint32_t* kOff = s32 + C2_PS;
    const int bid = blockIdx.x;
    const int gy0 = (bid >> 3) * 2, gx0 = (bid & 7) * 128;
    const int tid = threadIdx.x, lane = tid & 31, wid = tid >> 5;
    const int gid = lane >> 2, tig = lane & 3;

    for (int i = tid; i < C2_PS; i += 256) {
        uint32_t v = 0u;
        if (i < 9504) {
            int cp = i / 792, rem = i % 792, r = rem / 132, c = rem % 132;
            int gy = gy0 + r, gx = gx0 + c;
            if (gy < W1F && gx < W1F) v = H1[(size_t)cp * H1SZ + gy * W1F + gx];
        }
        s32[i] = v;
    }
    for (int p = tid; p < 320; p += 256) {
        int k = 2 * p;
        uint32_t v = 9504u;
        if (k < 600) { int tap = k / 24, cp = (k % 24) >> 1;
                       v = cp * 792 + (tap / 5) * 132 + (tap % 5); }
        kOff[p] = v;
    }
    int ro[2][2], mm[2][2];
#pragma unroll
    for (int t = 0; t < 2; t++)
#pragma unroll
        for (int h = 0; h < 2; h++) {
            int m = wid * 32 + t * 16 + gid + h * 8;
            mm[t][h] = m;
            ro[t][h] = (m >> 7) * 132 + (m & 127);
        }
    __syncthreads();

    float acc[2][8][4];
#pragma unroll
    for (int t = 0; t < 2; t++)
#pragma unroll
        for (int nt = 0; nt < 8; nt++)
#pragma unroll
            for (int j = 0; j < 4; j++) acc[t][nt][j] = 0.f;

    for (int kcl = 0; kcl < 40; kcl++) {
        uint32_t ko0 = kOff[kcl * 8 + tig], ko1 = kOff[kcl * 8 + tig + 4];
        uint32_t a[2][4];
#pragma unroll
        for (int t = 0; t < 2; t++) {
            a[t][0] = s32[ko0 + ro[t][0]];
            a[t][1] = s32[ko0 + ro[t][1]];
            a[t][2] = s32[ko1 + ro[t][0]];
            a[t][3] = s32[ko1 + ro[t][1]];
        }
#pragma unroll
        for (int nt = 0; nt < 8; nt++) {
            uint2 bd = __ldg(&g_Bc[(kcl * 8 + nt) * 32 + lane]);
#pragma unroll
            for (int t = 0; t < 2; t++)
                mma_f16(acc[t][nt], a[t], bd.x, bd.y);
        }
    }
#pragma unroll
    for (int t = 0; t < 2; t++)
#pragma unroll
        for (int nt = 0; nt < 8; nt++) {
            int n0 = nt * 8 + tig * 2;
            int cp = n0 >> 1;
#pragma unroll
            for (int h = 0; h < 2; h++) {
                int m = mm[t][h];
                int row = gy0 + (m >> 7), col = gx0 + (m & 127);
                if (row < W2F && col < W2F && n0 < 60) {
                    float v0 = acc[t][nt][h * 2]     + __ldg(&bias[n0]);
                    float v1 = acc[t][nt][h * 2 + 1] + __ldg(&bias[n0 + 1]);
                    H2[(size_t)cp * H2SZ + row * W2F + col] =
                        hpack(fmaxf(v0, 0.f), fmaxf(v1, 0.f));
                }
            }
        }
}

// ---------------- K3: deconv2 one-CTA-per-patch GEMM, pixel-major staging ----------------
// s32[pix(29x29=841) * 34 + q] ; q 0..29 = channel-pair planes, 30..33 zero pad.
// 10 warps x t=4 m-tiles (M=640), nt=3, K=1600 (100 clusters).
#define D2_PS 28596          // 841*34 rounded to mult of 4
#define D2_SMEM (D2_PS * 4)
__global__ void __launch_bounds__(320, 1)
deconv2_mma_kernel(const uint32_t* __restrict__ H2, const float* __restrict__ bias,
                   float* __restrict__ h3) {
    extern __shared__ uint32_t s32[];
    const int n = blockIdx.x;
    const int gy0 = (n / NHH) * 16, gx0 = (n % NHH) * 16;
    const int tid = threadIdx.x, lane = tid & 31, wid = tid >> 5;
    const int gid = lane >> 2, tig = lane & 3;

    // phase A: zero-fill (vectorized, conflict-free)
    uint4* s4 = reinterpret_cast<uint4*>(s32);
    for (int i = tid; i < D2_PS / 4; i += 320) s4[i] = make_uint4(0, 0, 0, 0);
    __syncthreads();
    // phase B: data fill, x-inner (coalesced LDG, 2-way STS conflicts)
    for (int i = tid; i < 30 * 441; i += 320) {
        int cp = i / 441, rem = i % 441, y = rem / 21, x = rem % 21;
        s32[((y + 4) * 29 + (x + 4)) * 34 + cp] =
            H2[(size_t)cp * H2SZ + (gy0 + y) * W2F + (gx0 + x)];
    }
    int pixB[4][2], mm[4][2];
#pragma unroll
    for (int t = 0; t < 4; t++)
#pragma unroll
        for (int h = 0; h < 2; h++) {
            int m = wid * 64 + t * 16 + gid + 8 * h;
            mm[t][h] = m;
            pixB[t][h] = (m < 625) ? ((m / 25) * 29 + m % 25) : 0;
        }
    __syncthreads();

    float acc[4][3][4];
#pragma unroll
    for (int t = 0; t < 4; t++)
#pragma unroll
        for (int nt = 0; nt < 3; nt++)
#pragma unroll
            for (int j = 0; j < 4; j++) acc[t][nt][j] = 0.f;

    const uint2* bptr = g_Bd2 + lane;
    for (int kcl = 0; kcl < 100; kcl++) {
        int tap = kcl >> 2, c = kcl & 3;
        int ky = (tap * 52) >> 8;              // tap / 5
        int tapAdd = ky * 24 + tap;            // ky*29 + (tap - 5*ky)
        int qb = c * 8 + 2 * tig;
        uint32_t a[4][4];
#pragma unroll
        for (int t = 0; t < 4; t++) {
            ull w0 = *reinterpret_cast<const ull*>(&s32[(pixB[t][0] + tapAdd) * 34 + qb]);
            ull w1 = *reinterpret_cast<const ull*>(&s32[(pixB[t][1] + tapAdd) * 34 + qb]);
            a[t][0] = (uint32_t)w0;  a[t][2] = (uint32_t)(w0 >> 32);
            a[t][1] = (uint32_t)w1;  a[t][3] = (uint32_t)(w1 >> 32);
        }
#pragma unroll
        for (int nt = 0; nt < 3; nt++) {
            uint2 bd = __ldg(bptr + (kcl * 3 + nt) * 32);
#pragma unroll
            for (int t = 0; t < 4; t++)
                mma_f16(acc[t][nt], a[t], bd.x, bd.y);
        }
    }
    float* pb = h3 + (size_t)n * 15000;
#pragma unroll
    for (int t = 0; t < 4; t++)
#pragma unroll
        for (int nt = 0; nt < 3; nt++) {
            int n0 = nt * 8 + tig * 2;   // 0..22
#pragma unroll
            for (int h = 0; h < 2; h++) {
                int m = mm[t][h];
                if (m < 625) {
                    float v0 = elu1(acc[t][nt][h * 2]     + __ldg(&bias[n0]));
                    float v1 = elu1(acc[t][nt][h * 2 + 1] + __ldg(&bias[n0 + 1]));
                    reinterpret_cast<float2*>(pb)[(n0 >> 1) * 625 + m] = make_float2(v0, v1);
                }
            }
        }
}

// ---------------- K4: deconv1 + einsum + bias (FFMA2), y-split occ2 ----------------
#define K4_SMEM 92256
__global__ void __launch_bounds__(256, 2)
deconv1_p_kernel(const float* __restrict__ h3, const float* __restrict__ w1,
                 const float* __restrict__ b1, const float* __restrict__ lin_w,
                 const float* __restrict__ lin_b, float* __restrict__ P) {
    extern __shared__ ull sm[];
    ull* sIn = sm;  // 12*897 = 10764
    float2* sWf = reinterpret_cast<float2*>(sm + 10764);
    const int bid = blockIdx.x;
    const int n = bid >> 1, half = bid & 1;
    const float lw0 = lin_w[2 * n], lw1 = lin_w[2 * n + 1];
    for (int i = threadIdx.x; i < 10764; i += 256) sIn[i] = 0ull;
    __syncthreads();
    const float2* p0 = reinterpret_cast<const float2*>(h3 + (size_t)n * 15000);
    for (int i = threadIdx.x; i < 12 * 16 * 25; i += 256) {
        int cp = i / 400, rem = i % 400, lr = rem / 25, x = rem % 25;
        int img_y = lr + (half ? 9 : 0);
        int l = img_y + 7 - half * 16;
        float2 a = p0[cp * 625 + img_y * 25 + x];
        sIn[cp * 897 + l * 39 + x + 7] =
            ((ull)__float_as_uint(a.y) << 32) | (ull)__float_as_uint(a.x);
    }
    for (int i = threadIdx.x; i < 768; i += 256) {
        int cp = i >> 6, rem = i & 63;
        int ky = rem >> 3, kx = rem & 7;
        int f0 = (2 * cp) * 128 + (7 - ky) * 8 + (7 - kx);
        int f1 = (2 * cp + 1) * 128 + (7 - ky) * 8 + (7 - kx);
        sWf[i] = make_float2(lw0 * w1[f0] + lw1 * w1[f0 + 64],
                             lw0 * w1[f1] + lw1 * w1[f1 + 64]);
    }
    __syncthreads();
    const ull* sW = reinterpret_cast<const ull*>(sWf);
    const float cst = (lw0 + lw1) * b1[0] + lin_b[n];
    const int t = threadIdx.x;
    const int yl = t >> 4;
    const int x0 = (t & 15) * 2;
    ull acc0 = 0ull, acc1 = 0ull;
    for (int cp = 0; cp < 12; cp++) {
#pragma unroll
        for (int ky = 0; ky < 8; ky++) {
            ull reg[9];
            const ull* row = sIn + cp * 897 + (yl + ky) * 39 + x0;
#pragma unroll
            for (int i = 0; i < 9; i++) reg[i] = row[i];
            const ull* wr = sW + cp * 64 + ky * 8;
#pragma unroll
            for (int kx = 0; kx < 8; kx++) {
                ull wv = wr[kx];
                fma2(acc0, reg[kx], wv);
                fma2(acc1, reg[kx + 1], wv);
            }
        }
    }
    float* outp = P + (size_t)n * 1024 + (half * 16 + yl) * 32 + x0;
    outp[0] = lo_f(acc0) + hi_f(acc0) + cst;
    outp[1] = lo_f(acc1) + hi_f(acc1) + cst;
}

// ---------------- K5: overlap-add + residual ----------------
__global__ void final_kernel(const float* __restrict__ x2, const float* __restrict__ P,
                             const float* __restrict__ linear1_w, float* __restrict__ out) {
    int idx = blockIdx.x * blockDim.x + threadIdx.x;
    if (idx >= HH * WW) return;
    int Y = idx >> 10, X = idx & 1023;
    float s = 0.f;
    int iy = Y >> 4, ix = X >> 4;
#pragma unroll
    for (int di = 0; di < 2; di++) {
        int i = iy - di;
        if (i < 0 || i > 62) continue;
        int py = Y - i * 16;
        if (py >= 32) continue;
#pragma unroll
        for (int dj = 0; dj < 2; dj++) {
            int j = ix - dj;
            if (j < 0 || j > 62) continue;
            int px = X - j * 16;
            if (px >= 32) continue;
            s += P[(size_t)(i * NHH + j) * 1024 + py * 32 + px];
        }
    }
    out[idx] = x2[idx] - s * linear1_w[0];
}

// ---------------------------------------------------------------------------
extern "C" void kernel_launch(void* const* d_in, const int* in_sizes, int n_in,
                              void* d_out, int out_size) {
    const float* x1        = (const float*)d_in[0];
    const float* x2        = (const float*)d_in[1];
    const float* conv1_w   = (const float*)d_in[2];
    const float* conv1_b   = (const float*)d_in[3];
    const float* conv2_w   = (const float*)d_in[4];
    const float* conv2_b   = (const float*)d_in[5];
    const float* deconv2_w = (const float*)d_in[6];
    const float* deconv2_b = (const float*)d_in[7];
    const float* deconv1_w = (const float*)d_in[8];
    const float* deconv1_b = (const float*)d_in[9];
    const float* lin_w     = (const float*)d_in[10];
    const float* lin_b     = (const float*)d_in[11];
    const float* linear1_w = (const float*)d_in[12];
    float* out = (float*)d_out;

    uint32_t *H1, *H2;
    float *h3, *P;
    cudaGetSymbolAddress((void**)&H1, g_H1);
    cudaGetSymbolAddress((void**)&H2, g_H2);
    cudaGetSymbolAddress((void**)&h3, g_h3);
    cudaGetSymbolAddress((void**)&P,  g_p);

    cudaFuncSetAttribute(conv2_full_kernel,  cudaFuncAttributeMaxDynamicSharedMemorySize, C2_SMEM);
    cudaFuncSetAttribute(deconv2_mma_kernel, cudaFuncAttributeMaxDynamicSharedMemorySize, D2_SMEM);
    cudaFuncSetAttribute(deconv1_p_kernel,   cudaFuncAttributeMaxDynamicSharedMemorySize, K4_SMEM);

    pack_kernel<<<(10240 + 9600 + 255) / 256, 256>>>(conv2_w, deconv2_w);
    conv1_full_kernel<<<dim3(16, 64), 256>>>(x1, x2, conv1_w, conv1_b, H1);
    conv2_full_kernel<<<507 * 8, 256, C2_SMEM>>>(H1, conv2_b, H2);
    deconv2_mma_kernel<<<NP, 320, D2_SMEM>>>(H2, deconv2_b, h3);
    deconv1_p_kernel<<<NP * 2, 256, K4_SMEM>>>(h3, deconv1_w, deconv1_b, lin_w, lin_b, P);
    final_kernel<<<(HH * WW + 255) / 256, 256>>>(x2, P, linear1_w, out);
}